// round 1
// baseline (speedup 1.0000x reference)
#include <cuda_runtime.h>

#define TT 300
#define NB 4

// ---------------- static device buffers (no allocation allowed) ----------------
__device__ unsigned long long g_r0[TT*NB*2*34];        // input row masks, bit (x+2)
__device__ unsigned int       g_M1[TT*NB*1156];        // spikes1: 24 ch bits, 34x34
__device__ unsigned int       g_M2[TT*NB*289];         // spikes2: 24 ch bits, 17x17
__device__ unsigned long long g_M3[TT*NB*289];         // spikes3: 48 ch bits, 17x17
__device__ unsigned int       g_M4[TT*NB*81*2];        // spikes4: 48 ch bits (2 words), 9x9
__device__ unsigned int       g_M5[TT*NB*81*3];        // spikes5: 96 ch bits (3 words), 9x9
__device__ unsigned int       g_M6[TT*NB*25*3];        // spikes6: 96 ch bits (3 words), 5x5
__device__ float              g_A7[TT*NB*256];         // dense1 pre-activation
__device__ unsigned int       g_M7[TT*NB*8];           // spikes7: 256 bits
__device__ float              g_A8[TT*NB*16];          // dense2 pre-activation (padded)
__device__ float g_Wt1[50*32];      // [ky][bit(c,kx)][o pad32]
__device__ float g_Wt2[216*64];     // [(c*9+kt)][o pad64]
__device__ float g_Wt3[432*96];     // [(c*9+kt)][o 96]
__device__ float g_Wt4[2400*256];   // [(c*25+pos)][o 256]
__device__ float g_Wt5[256*16];     // [i][o pad16]

// ---------------- SRM: psp (tau=10) + spike w/ refractory (tau=1) ----------------
__device__ __forceinline__ float srm_step(float& p1, float& q1, float& p2, float& q2, float x) {
    const float A1 = 0.90483741803595952f;   // exp(-1/10)
    const float C1 = 0.27182818284590452f;   // e/10
    const float A2 = 0.36787944117144233f;   // exp(-1)
    const float C2 = 2.71828182845904523f;   // e
    const float RR = 20.0f * C2;             // SCALE_REF*THETA*c
    q1 = A1*q1 + A1*p1;
    p1 = A1*p1 + x;
    float y = C1 * q1;
    q2 = A2*q2 + A2*p2;
    float u = y - RR*q2;
    float s = (u >= 10.0f) ? 1.0f : 0.0f;
    p2 = A2*p2 + s;
    return s;
}

// ---------------- weight transpose / pad ----------------
__global__ void prep_weights(const float* __restrict__ Wc1, const float* __restrict__ Wc2,
                             const float* __restrict__ Wc3, const float* __restrict__ Wd4a,
                             const float* __restrict__ Wd4b) {
    int i = blockIdx.x * blockDim.x + threadIdx.x;
    if (i < 50*32) {
        int tap = i >> 5, o = i & 31;
        int ky = tap / 10, bit = tap % 10, c = bit / 5, kx = bit % 5;
        g_Wt1[i] = (o < 24) ? Wc1[o*50 + c*25 + ky*5 + kx] : 0.f;
    }
    if (i < 216*64) {
        int tap = i >> 6, o = i & 63;
        g_Wt2[i] = (o < 48) ? Wc2[o*216 + tap] : 0.f;
    }
    if (i < 432*96) {
        int tap = i / 96, o = i % 96;
        g_Wt3[i] = Wc3[o*432 + tap];
    }
    if (i < 2400*256) {
        int r = i >> 8, o = i & 255;
        g_Wt4[i] = Wd4a[o*2400 + r];
    }
    if (i < 256*16) {
        int r = i >> 4, o = i & 15;
        g_Wt5[i] = (o < 10) ? Wd4b[o*256 + r] : 0.f;
    }
}

// ---------------- pack s_in (B,2,34,34,T) float -> row bitmasks [t][b][c][y] ----------------
__global__ void pack_input(const float* __restrict__ s_in) {
    int idx = blockIdx.x * blockDim.x + threadIdx.x;
    if (idx >= NB*2*34*TT) return;
    int t = idx % TT;
    int r = idx / TT;
    int y = r % 34; r /= 34;
    int c = r % 2;
    int b = r / 2;
    const float* sp = s_in + ((size_t)((b*2 + c)*34 + y)*34)*TT + t;
    unsigned long long m = 0ull;
    for (int x = 0; x < 34; x++)
        if (sp[(size_t)x*TT] != 0.f) m |= (1ull << (x + 2));
    g_r0[((size_t)(t*NB + b)*2 + c)*34 + y] = m;
}

// ---------------- conv1 (2->24, 5x5, pad2, 34x34) fused with SRM ----------------
__global__ void conv1_srm() {
    int gt = blockIdx.x * blockDim.x + threadIdx.x;
    int w = gt >> 5, lane = gt & 31;
    if (w >= NB*1156) return;
    int b = w / 1156, rem = w % 1156, y = rem / 34, x = rem % 34;
    int ky0 = (y >= 2) ? 0 : (2 - y);
    int ky1 = (y <= 31) ? 5 : (36 - y);
    float p1 = 0, q1 = 0, p2 = 0, q2 = 0;
    for (int t = 0; t < TT; t++) {
        const unsigned long long* rt = g_r0 + (size_t)(t*NB + b)*68;
        float acc = 0.f;
        for (int ky = ky0; ky < ky1; ky++) {
            int yy = y + ky - 2;
            unsigned int f = ((unsigned int)(rt[yy] >> x) & 31u)
                           | ((((unsigned int)(rt[34 + yy] >> x)) & 31u) << 5);
            const float* wr = g_Wt1 + ky*320;
            while (f) { int bit = __ffs(f) - 1; f &= f - 1; acc += wr[(bit << 5) + lane]; }
        }
        float s = srm_step(p1, q1, p2, q2, acc);
        unsigned bal = __ballot_sync(0xffffffffu, s > 0.5f);
        if (!lane) g_M1[(size_t)(t*NB + b)*1156 + rem] = bal;
    }
}

// ---------------- pool1 (24ch, 34->17) + SRM ----------------
__global__ void pool1_srm() {
    int gt = blockIdx.x * blockDim.x + threadIdx.x;
    int w = gt >> 5, lane = gt & 31;
    if (w >= NB*289) return;
    int b = w / 289, rem = w % 289, y = rem / 17, x = rem % 17;
    int p0 = (2*y)*34 + 2*x;
    float p1 = 0, q1 = 0, p2 = 0, q2 = 0;
    for (int t = 0; t < TT; t++) {
        const unsigned int* m = g_M1 + (size_t)(t*NB + b)*1156;
        int cnt = ((m[p0] >> lane) & 1) + ((m[p0 + 1] >> lane) & 1)
                + ((m[p0 + 34] >> lane) & 1) + ((m[p0 + 35] >> lane) & 1);
        float s = srm_step(p1, q1, p2, q2, 11.0f * (float)cnt);
        unsigned bal = __ballot_sync(0xffffffffu, s > 0.5f);
        if (!lane) g_M2[(size_t)(t*NB + b)*289 + rem] = bal;
    }
}

// ---------------- conv2 (24->48, 3x3, pad1, 17x17) + SRM ----------------
__global__ void conv2_srm() {
    int gt = blockIdx.x * blockDim.x + threadIdx.x;
    int w = gt >> 5, lane = gt & 31;
    if (w >= NB*289) return;
    int b = w / 289, rem = w % 289, y = rem / 17, x = rem % 17;
    int n = 0, moff[9], wb[9];
    for (int ky = 0; ky < 3; ky++)
        for (int kx = 0; kx < 3; kx++) {
            int yy = y + ky - 1, xx = x + kx - 1;
            if (yy >= 0 && yy < 17 && xx >= 0 && xx < 17) {
                moff[n] = yy*17 + xx; wb[n] = (ky*3 + kx)*64; n++;
            }
        }
    float pa1=0,qa1=0,pa2=0,qa2=0, pb1=0,qb1=0,pb2=0,qb2=0;
    for (int t = 0; t < TT; t++) {
        const unsigned int* mm = g_M2 + (size_t)(t*NB + b)*289;
        float aa = 0.f, ab = 0.f;
        for (int j = 0; j < n; j++) {
            unsigned int m = mm[moff[j]];
            const float* wt = g_Wt2 + wb[j];
            while (m) {
                int c = __ffs(m) - 1; m &= m - 1;
                const float* wp = wt + c*576;
                aa += wp[lane];
                ab += wp[lane + 32];
            }
        }
        float sa = srm_step(pa1, qa1, pa2, qa2, aa);
        float sb = srm_step(pb1, qb1, pb2, qb2, ab);
        unsigned b0 = __ballot_sync(0xffffffffu, sa > 0.5f);
        unsigned b1 = __ballot_sync(0xffffffffu, sb > 0.5f);
        if (!lane) g_M3[(size_t)(t*NB + b)*289 + rem]
                       = (unsigned long long)b0 | ((unsigned long long)b1 << 32);
    }
}

// ---------------- pool2 (48ch, 17->9, zero-pad) + SRM ----------------
__global__ void pool2_srm() {
    int gt = blockIdx.x * blockDim.x + threadIdx.x;
    int w = gt >> 5, lane = gt & 31;
    if (w >= NB*81*2) return;
    int wrd = w & 1, pix = w >> 1;
    int b = pix / 81, rem = pix % 81, y = rem / 9, x = rem % 9;
    bool xv = (2*x + 1) < 17, yv = (2*y + 1) < 17;
    int p00 = 2*y*17 + 2*x;
    int c = wrd*32 + lane;
    float p1=0,q1=0,p2=0,q2=0;
    for (int t = 0; t < TT; t++) {
        const unsigned long long* m = g_M3 + (size_t)(t*NB + b)*289;
        unsigned long long m00 = m[p00];
        unsigned long long m01 = xv ? m[p00 + 1] : 0ull;
        unsigned long long m10 = yv ? m[p00 + 17] : 0ull;
        unsigned long long m11 = (xv && yv) ? m[p00 + 18] : 0ull;
        int cnt = (int)((m00 >> c) & 1) + (int)((m01 >> c) & 1)
                + (int)((m10 >> c) & 1) + (int)((m11 >> c) & 1);
        float s = srm_step(p1, q1, p2, q2, 11.0f * (float)cnt);
        unsigned bal = __ballot_sync(0xffffffffu, s > 0.5f);
        if (!lane) g_M4[((size_t)(t*NB + b)*81 + rem)*2 + wrd] = bal;
    }
}

// ---------------- conv3 (48->96, 3x3, pad1, 9x9) + SRM. block=96 threads, 1 pixel ----------------
__global__ void conv3_srm() {
    int pixg = blockIdx.x;                 // 0..NB*81-1
    int b = pixg / 81, rem = pixg % 81, y = rem / 9, x = rem % 9;
    int o = threadIdx.x, lane = o & 31;
    int n = 0, moff[9], wb[9];
    for (int ky = 0; ky < 3; ky++)
        for (int kx = 0; kx < 3; kx++) {
            int yy = y + ky - 1, xx = x + kx - 1;
            if (yy >= 0 && yy < 9 && xx >= 0 && xx < 9) {
                moff[n] = (yy*9 + xx)*2; wb[n] = (ky*3 + kx)*96; n++;
            }
        }
    float p1=0,q1=0,p2=0,q2=0;
    for (int t = 0; t < TT; t++) {
        const unsigned int* mm = g_M4 + (size_t)(t*NB + b)*162;
        float acc = 0.f;
        for (int j = 0; j < n; j++) {
            unsigned int mlo = mm[moff[j]], mhi = mm[moff[j] + 1];
            const float* wt = g_Wt3 + wb[j] + o;
            while (mlo) { int c = __ffs(mlo) - 1; mlo &= mlo - 1; acc += wt[c*864]; }
            while (mhi) { int c = __ffs(mhi) - 1; mhi &= mhi - 1; acc += wt[(c + 32)*864]; }
        }
        float s = srm_step(p1, q1, p2, q2, acc);
        unsigned bal = __ballot_sync(0xffffffffu, s > 0.5f);
        if (!lane) g_M5[((size_t)(t*NB + b)*81 + rem)*3 + (threadIdx.x >> 5)] = bal;
    }
}

// ---------------- pool3 (96ch, 9->5, zero-pad) + SRM ----------------
__global__ void pool3_srm() {
    int gt = blockIdx.x * blockDim.x + threadIdx.x;
    int w = gt >> 5, lane = gt & 31;
    if (w >= NB*25*3) return;
    int wrd = w % 3, pix = w / 3;
    int b = pix / 25, rem = pix % 25, y = rem / 5, x = rem % 5;
    bool xv = (2*x + 1) < 9, yv = (2*y + 1) < 9;
    int p00 = 2*y*9 + 2*x;
    float p1=0,q1=0,p2=0,q2=0;
    for (int t = 0; t < TT; t++) {
        const unsigned int* m = g_M5 + (size_t)(t*NB + b)*243;
        unsigned int m00 = m[p00*3 + wrd];
        unsigned int m01 = xv ? m[(p00 + 1)*3 + wrd] : 0u;
        unsigned int m10 = yv ? m[(p00 + 9)*3 + wrd] : 0u;
        unsigned int m11 = (xv && yv) ? m[(p00 + 10)*3 + wrd] : 0u;
        int cnt = ((m00 >> lane) & 1) + ((m01 >> lane) & 1)
                + ((m10 >> lane) & 1) + ((m11 >> lane) & 1);
        float s = srm_step(p1, q1, p2, q2, 11.0f * (float)cnt);
        unsigned bal = __ballot_sync(0xffffffffu, s > 0.5f);
        if (!lane) g_M6[((size_t)(t*NB + b)*25 + rem)*3 + wrd] = bal;
    }
}

// ---------------- dense1 (2400->256): parallel over all (t,b) ----------------
__global__ void dense1() {
    int tb = blockIdx.x;            // t*NB+b
    int o = threadIdx.x;            // 0..255
    const unsigned int* m = g_M6 + (size_t)tb*75;
    float acc = 0.f;
    for (int pos = 0; pos < 25; pos++)
        for (int wd = 0; wd < 3; wd++) {
            unsigned int mm = m[pos*3 + wd];
            const float* wt = g_Wt4 + pos*256 + o;
            int cb = wd*32;
            while (mm) { int c = cb + __ffs(mm) - 1; mm &= mm - 1; acc += wt[(size_t)c*6400]; }
        }
    g_A7[(size_t)tb*256 + o] = acc;
}

// ---------------- SRM for dense1 (256 neurons x B) ----------------
__global__ void srm_d1() {
    int b = blockIdx.x;
    int o = threadIdx.x, lane = o & 31;
    float p1=0,q1=0,p2=0,q2=0;
    for (int t = 0; t < TT; t++) {
        float x = g_A7[(size_t)(t*NB + b)*256 + o];
        float s = srm_step(p1, q1, p2, q2, x);
        unsigned bal = __ballot_sync(0xffffffffu, s > 0.5f);
        if (!lane) g_M7[(size_t)(t*NB + b)*8 + (o >> 5)] = bal;
    }
}

// ---------------- dense2 (256->10): parallel over (t,b) ----------------
__global__ void dense2() {
    int tb = blockIdx.x;
    int lane = threadIdx.x;
    if (lane < 16) {
        const unsigned int* m = g_M7 + (size_t)tb*8;
        float acc = 0.f;
        for (int wd = 0; wd < 8; wd++) {
            unsigned int mm = m[wd];
            int ib = wd*32;
            while (mm) { int i = ib + __ffs(mm) - 1; mm &= mm - 1; acc += g_Wt5[i*16 + lane]; }
        }
        g_A8[(size_t)tb*16 + lane] = acc;
    }
}

// ---------------- final SRM -> output spikes (B,10,T) float ----------------
__global__ void srm_out(float* __restrict__ out) {
    int tid = threadIdx.x;
    if (tid >= 40) return;
    int b = tid / 10, o = tid % 10;
    float p1=0,q1=0,p2=0,q2=0;
    for (int t = 0; t < TT; t++) {
        float x = g_A8[(size_t)(t*NB + b)*16 + o];
        float s = srm_step(p1, q1, p2, q2, x);
        out[(size_t)(b*10 + o)*TT + t] = s;
    }
}

extern "C" void kernel_launch(void* const* d_in, const int* in_sizes, int n_in,
                              void* d_out, int out_size) {
    const float* s_in = (const float*)d_in[0];
    const float* Wc1  = (const float*)d_in[1];
    const float* Wc2  = (const float*)d_in[2];
    const float* Wc3  = (const float*)d_in[3];
    const float* Wd4a = (const float*)d_in[4];
    const float* Wd4b = (const float*)d_in[5];
    float* out = (float*)d_out;

    prep_weights<<<2400, 256>>>(Wc1, Wc2, Wc3, Wd4a, Wd4b);
    pack_input<<<(NB*2*34*TT + 255)/256, 256>>>(s_in);
    conv1_srm<<<(NB*1156*32 + 255)/256, 256>>>();
    pool1_srm<<<(NB*289*32 + 255)/256, 256>>>();
    conv2_srm<<<(NB*289*32 + 255)/256, 256>>>();
    pool2_srm<<<(NB*81*2*32 + 255)/256, 256>>>();
    conv3_srm<<<NB*81, 96>>>();
    pool3_srm<<<(NB*25*3*32 + 255)/256, 256>>>();
    dense1<<<TT*NB, 256>>>();
    srm_d1<<<NB, 256>>>();
    dense2<<<TT*NB, 32>>>();
    srm_out<<<1, 64>>>(out);
}

// round 2
// speedup vs baseline: 4.6141x; 4.6141x over previous
#include <cuda_runtime.h>

#define TT 300
#define NB 4

// ---------------- static device buffers ----------------
__device__ unsigned long long g_r0[TT*NB*2*34];      // input row masks, bit (x+2)
__device__ unsigned int g_M1[TT*NB*1156];            // spikes L1: 24ch bits / pixel
__device__ unsigned int g_M2[TT*NB*289];             // spikes P1
__device__ unsigned int g_M3[TT*NB*289*2];           // spikes L2: 48ch in 2 words
__device__ unsigned int g_M4[TT*NB*81*2];            // spikes P2
__device__ unsigned int g_M5[TT*NB*81*3];            // spikes L3: 96ch in 3 words
__device__ unsigned int g_M6[TT*NB*25*3];            // spikes P3
__device__ unsigned int g_M7[TT*NB*8];               // spikes dense1: 256 bits

__device__ float g_A1[(size_t)TT*NB*1156*32];        // conv1 pre-act (pad 24->32)
__device__ float g_P1[(size_t)TT*NB*289*32];         // pool1 pre-act
__device__ float g_A2[(size_t)TT*NB*289*64];         // conv2 pre-act (pad 48->64)
__device__ float g_P2[(size_t)TT*NB*81*64];          // pool2 pre-act
__device__ float g_A3[(size_t)TT*NB*81*96];          // conv3 pre-act
__device__ float g_P3[(size_t)TT*NB*25*96];          // pool3 pre-act
__device__ float g_A7[TT*NB*256];                    // dense1 pre-act
__device__ float g_A8[TT*NB*32];                     // dense2 pre-act (pad 10->32)

__device__ float g_Wt1[50*32];      // [(ky*10 + c*5+kx)][o pad32]
__device__ float g_Wt2[216*64];     // [(c*9+kt)][o pad64]
__device__ float g_Wt3[432*96];     // [(c*9+kt)][o 96]
__device__ float g_Wt4[2400*256];   // [(c*25+pos)][o 256]
__device__ float g_Wt5[256*16];     // [i][o pad16]

// ---------------- SRM step: psp (tau=10) + spike w/ refractory (tau=1) ----------------
__device__ __forceinline__ float srm_step(float& p1, float& q1, float& p2, float& q2, float x) {
    const float A1 = 0.90483741803595952f;   // exp(-1/10)
    const float C1 = 0.27182818284590452f;   // e/10
    const float A2 = 0.36787944117144233f;   // exp(-1)
    const float C2 = 2.71828182845904523f;   // e
    const float RR = 20.0f * C2;             // SCALE_REF*THETA*c
    q1 = A1*q1 + A1*p1;
    p1 = A1*p1 + x;
    float y = C1 * q1;
    q2 = A2*q2 + A2*p2;
    float u = y - RR*q2;
    float s = (u >= 10.0f) ? 1.0f : 0.0f;
    p2 = A2*p2 + s;
    return s;
}

// ---------------- generic SRM scan: warp = 32 neurons, prefetch ring depth 8 ----------------
__device__ __forceinline__ void srm_scan_body(const float* __restrict__ in,
                                              unsigned int* __restrict__ out, int nW) {
    int w = blockIdx.x * (blockDim.x >> 5) + (threadIdx.x >> 5);
    int lane = threadIdx.x & 31;
    if (w >= nW) return;
    const float* ip = in + (size_t)w*32 + lane;
    size_t S = (size_t)nW * 32;
    const int PF = 8;
    float buf[PF];
#pragma unroll
    for (int k = 0; k < PF; k++) buf[k] = ip[(size_t)k*S];
    float p1=0,q1=0,p2=0,q2=0;
    for (int t0 = 0; t0 < TT; t0 += PF) {
#pragma unroll
        for (int k = 0; k < PF; k++) {
            int t = t0 + k;
            if (t >= TT) break;
            float x = buf[k];
            int tn = t + PF;
            buf[k] = (tn < TT) ? ip[(size_t)tn*S] : 0.f;
            float s = srm_step(p1, q1, p2, q2, x);
            unsigned bal = __ballot_sync(0xffffffffu, s > 0.5f);
            if (!lane) out[(size_t)t*nW + w] = bal;
        }
    }
}

__global__ void __launch_bounds__(256) srm_scan_L1() { srm_scan_body(g_A1, g_M1, NB*1156);   }
__global__ void __launch_bounds__(256) srm_scan_P1() { srm_scan_body(g_P1, g_M2, NB*289);    }
__global__ void __launch_bounds__(256) srm_scan_L2() { srm_scan_body(g_A2, g_M3, NB*289*2);  }
__global__ void __launch_bounds__(256) srm_scan_P2() { srm_scan_body(g_P2, g_M4, NB*81*2);   }
__global__ void __launch_bounds__(256) srm_scan_L3() { srm_scan_body(g_A3, g_M5, NB*81*3);   }
__global__ void __launch_bounds__(256) srm_scan_P3() { srm_scan_body(g_P3, g_M6, NB*25*3);   }
__global__ void __launch_bounds__(256) srm_scan_D1() { srm_scan_body(g_A7, g_M7, NB*8);      }

// ---------------- weight transpose / pad ----------------
__global__ void prep_weights(const float* __restrict__ Wc1, const float* __restrict__ Wc2,
                             const float* __restrict__ Wc3, const float* __restrict__ Wd4a,
                             const float* __restrict__ Wd4b) {
    int i = blockIdx.x * blockDim.x + threadIdx.x;
    if (i < 50*32) {
        int tap = i >> 5, o = i & 31;
        int ky = tap / 10, bit = tap % 10, c = bit / 5, kx = bit % 5;
        g_Wt1[i] = (o < 24) ? Wc1[o*50 + c*25 + ky*5 + kx] : 0.f;
    }
    if (i < 216*64) {
        int tap = i >> 6, o = i & 63;
        g_Wt2[i] = (o < 48) ? Wc2[o*216 + tap] : 0.f;
    }
    if (i < 432*96) {
        int tap = i / 96, o = i % 96;
        g_Wt3[i] = Wc3[o*432 + tap];
    }
    if (i < 2400*256) {
        int r = i >> 8, o = i & 255;
        g_Wt4[i] = Wd4a[o*2400 + r];
    }
    if (i < 256*16) {
        int r = i >> 4, o = i & 15;
        g_Wt5[i] = (o < 10) ? Wd4b[o*256 + r] : 0.f;
    }
}

// ---------------- pack s_in (B,2,34,34,T) -> row bitmasks [t][b][c][y] ----------------
__global__ void pack_input(const float* __restrict__ s_in) {
    int idx = blockIdx.x * blockDim.x + threadIdx.x;
    if (idx >= NB*2*34*TT) return;
    int t = idx % TT;
    int r = idx / TT;
    int y = r % 34; r /= 34;
    int c = r % 2;
    int b = r / 2;
    const float* sp = s_in + ((size_t)((b*2 + c)*34 + y)*34)*TT + t;
    unsigned long long m = 0ull;
    for (int x = 0; x < 34; x++)
        if (sp[(size_t)x*TT] != 0.f) m |= (1ull << (x + 2));
    g_r0[((size_t)(t*NB + b)*2 + c)*34 + y] = m;
}

// ---------------- conv1 acc (2->24, 5x5, pad2): warp per (t,b,pixel) ----------------
__global__ void __launch_bounds__(256) conv1_acc() {
    int gw = blockIdx.x * 8 + (threadIdx.x >> 5);
    int lane = threadIdx.x & 31;
    if (gw >= TT*NB*1156) return;
    int rem = gw % 1156, tb = gw / 1156;
    int y = rem / 34, x = rem % 34;
    int ky0 = (y >= 2) ? 0 : (2 - y);
    int ky1 = (y <= 31) ? 5 : (36 - y);
    const unsigned long long* rt = g_r0 + (size_t)tb*68;
    float acc = 0.f;
    for (int ky = ky0; ky < ky1; ky++) {
        int yy = y + ky - 2;
        unsigned int f = ((unsigned int)(rt[yy] >> x) & 31u)
                       | ((((unsigned int)(rt[34 + yy] >> x)) & 31u) << 5);
        const float* wr = g_Wt1 + ky*320;
        while (f) { int bit = __ffs(f) - 1; f &= f - 1; acc += wr[(bit << 5) + lane]; }
    }
    g_A1[(size_t)gw*32 + lane] = acc;
}

// ---------------- pool1 acc (24ch, 34->17): warp per (t,b,opix) ----------------
__global__ void __launch_bounds__(256) pool1_acc() {
    int gw = blockIdx.x * 8 + (threadIdx.x >> 5);
    int lane = threadIdx.x & 31;
    if (gw >= TT*NB*289) return;
    int opix = gw % 289, tb = gw / 289;
    int y = opix / 17, x = opix % 17;
    const unsigned int* m = g_M1 + (size_t)tb*1156;
    int p0 = 2*y*34 + 2*x;
    unsigned m00 = m[p0], m01 = m[p0+1], m10 = m[p0+34], m11 = m[p0+35];
    int cnt = ((m00>>lane)&1) + ((m01>>lane)&1) + ((m10>>lane)&1) + ((m11>>lane)&1);
    g_P1[(size_t)gw*32 + lane] = 11.0f * (float)cnt;
}

// ---------------- conv2 acc (24->48, 3x3, pad1, 17x17): warp per (t,b,pixel) ----------------
__global__ void __launch_bounds__(256) conv2_acc() {
    int gw = blockIdx.x * 8 + (threadIdx.x >> 5);
    int lane = threadIdx.x & 31;
    if (gw >= TT*NB*289) return;
    int rem = gw % 289, tb = gw / 289;
    int y = rem / 17, x = rem % 17;
    int n = 0, moff[9], ktl[9];
    for (int ky = 0; ky < 3; ky++)
        for (int kx = 0; kx < 3; kx++) {
            int yy = y + ky - 1, xx = x + kx - 1;
            if (yy >= 0 && yy < 17 && xx >= 0 && xx < 17) {
                moff[n] = yy*17 + xx; ktl[n] = ky*3 + kx; n++;
            }
        }
    const unsigned int* mm = g_M2 + (size_t)tb*289;
    float aa = 0.f, ab = 0.f;
    for (int j = 0; j < n; j++) {
        unsigned int m = mm[moff[j]];
        int kt = ktl[j];
        while (m) {
            int c = __ffs(m) - 1; m &= m - 1;
            const float* wp = g_Wt2 + (c*9 + kt)*64;
            aa += wp[lane];
            ab += wp[lane + 32];
        }
    }
    g_A2[(size_t)gw*64 + lane]      = aa;
    g_A2[(size_t)gw*64 + lane + 32] = ab;
}

// ---------------- pool2 acc (48ch, 17->9, zero-pad): warp per (t,b,opix,half) ----------------
__global__ void __launch_bounds__(256) pool2_acc() {
    int gw = blockIdx.x * 8 + (threadIdx.x >> 5);
    int lane = threadIdx.x & 31;
    if (gw >= TT*NB*81*2) return;
    int half = gw & 1;
    int opix = (gw >> 1) % 81, tb = gw / 162;
    int y = opix / 9, x = opix % 9;
    bool xv = (2*x + 1) < 17, yv = (2*y + 1) < 17;
    int p00 = 2*y*17 + 2*x;
    const unsigned int* m = g_M3 + (size_t)tb*578;
    unsigned m00 = m[p00*2 + half];
    unsigned m01 = xv ? m[(p00+1)*2 + half] : 0u;
    unsigned m10 = yv ? m[(p00+17)*2 + half] : 0u;
    unsigned m11 = (xv && yv) ? m[(p00+18)*2 + half] : 0u;
    int cnt = ((m00>>lane)&1) + ((m01>>lane)&1) + ((m10>>lane)&1) + ((m11>>lane)&1);
    g_P2[(size_t)gw*32 + lane] = 11.0f * (float)cnt;
}

// ---------------- conv3 acc (48->96, 3x3, pad1, 9x9): warp per (t,b,pixel), 3 outs/lane ----------------
__global__ void __launch_bounds__(256) conv3_acc() {
    int gw = blockIdx.x * 8 + (threadIdx.x >> 5);
    int lane = threadIdx.x & 31;
    if (gw >= TT*NB*81) return;
    int rem = gw % 81, tb = gw / 81;
    int y = rem / 9, x = rem % 9;
    int n = 0, moff[9], ktl[9];
    for (int ky = 0; ky < 3; ky++)
        for (int kx = 0; kx < 3; kx++) {
            int yy = y + ky - 1, xx = x + kx - 1;
            if (yy >= 0 && yy < 9 && xx >= 0 && xx < 9) {
                moff[n] = (yy*9 + xx)*2; ktl[n] = ky*3 + kx; n++;
            }
        }
    const unsigned int* mm = g_M4 + (size_t)tb*162;
    float a0 = 0.f, a1 = 0.f, a2 = 0.f;
    for (int j = 0; j < n; j++) {
        unsigned int mlo = mm[moff[j]], mhi = mm[moff[j] + 1];
        int kt = ktl[j];
        while (mlo) {
            int c = __ffs(mlo) - 1; mlo &= mlo - 1;
            const float* wp = g_Wt3 + (c*9 + kt)*96;
            a0 += wp[lane]; a1 += wp[lane+32]; a2 += wp[lane+64];
        }
        while (mhi) {
            int c = __ffs(mhi) - 1; mhi &= mhi - 1;
            const float* wp = g_Wt3 + ((c+32)*9 + kt)*96;
            a0 += wp[lane]; a1 += wp[lane+32]; a2 += wp[lane+64];
        }
    }
    g_A3[(size_t)gw*96 + lane]      = a0;
    g_A3[(size_t)gw*96 + lane + 32] = a1;
    g_A3[(size_t)gw*96 + lane + 64] = a2;
}

// ---------------- pool3 acc (96ch, 9->5, zero-pad): warp per (t,b,opix,wrd) ----------------
__global__ void __launch_bounds__(256) pool3_acc() {
    int gw = blockIdx.x * 8 + (threadIdx.x >> 5);
    int lane = threadIdx.x & 31;
    if (gw >= TT*NB*25*3) return;
    int wrd = gw % 3;
    int opix = (gw / 3) % 25, tb = gw / 75;
    int y = opix / 5, x = opix % 5;
    bool xv = (2*x + 1) < 9, yv = (2*y + 1) < 9;
    int p00 = 2*y*9 + 2*x;
    const unsigned int* m = g_M5 + (size_t)tb*243;
    unsigned m00 = m[p00*3 + wrd];
    unsigned m01 = xv ? m[(p00+1)*3 + wrd] : 0u;
    unsigned m10 = yv ? m[(p00+9)*3 + wrd] : 0u;
    unsigned m11 = (xv && yv) ? m[(p00+10)*3 + wrd] : 0u;
    int cnt = ((m00>>lane)&1) + ((m01>>lane)&1) + ((m10>>lane)&1) + ((m11>>lane)&1);
    g_P3[(size_t)gw*32 + lane] = 11.0f * (float)cnt;
}

// ---------------- dense1 (2400->256): block per (t,b) ----------------
__global__ void __launch_bounds__(256) dense1() {
    int tb = blockIdx.x;
    int o = threadIdx.x;
    const unsigned int* m = g_M6 + (size_t)tb*75;
    float acc = 0.f;
    for (int pos = 0; pos < 25; pos++)
        for (int wd = 0; wd < 3; wd++) {
            unsigned int mm = m[pos*3 + wd];
            const float* wt = g_Wt4 + pos*256 + o;
            int cb = wd*32;
            while (mm) { int c = cb + __ffs(mm) - 1; mm &= mm - 1; acc += wt[(size_t)c*6400]; }
        }
    g_A7[(size_t)tb*256 + o] = acc;
}

// ---------------- dense2 (256->10): warp per (t,b) ----------------
__global__ void __launch_bounds__(256) dense2() {
    int w = blockIdx.x * 8 + (threadIdx.x >> 5);
    int lane = threadIdx.x & 31;
    if (w >= TT*NB) return;
    float acc = 0.f;
    if (lane < 16) {
        const unsigned int* m = g_M7 + (size_t)w*8;
        for (int wd = 0; wd < 8; wd++) {
            unsigned int mm = m[wd];
            int ib = wd*32;
            while (mm) { int i = ib + __ffs(mm) - 1; mm &= mm - 1; acc += g_Wt5[i*16 + lane]; }
        }
    }
    if (lane < 32) g_A8[(size_t)w*32 + lane] = (lane < 16) ? acc : 0.f;
}

// ---------------- final SRM -> output spikes (B,10,T) ----------------
__global__ void srm_out(float* __restrict__ out) {
    int tid = threadIdx.x;
    if (tid >= 40) return;
    int b = tid / 10, o = tid % 10;
    float p1=0,q1=0,p2=0,q2=0;
    for (int t = 0; t < TT; t++) {
        float x = g_A8[(size_t)(t*NB + b)*32 + o];
        float s = srm_step(p1, q1, p2, q2, x);
        out[(size_t)(b*10 + o)*TT + t] = s;
    }
}

extern "C" void kernel_launch(void* const* d_in, const int* in_sizes, int n_in,
                              void* d_out, int out_size) {
    const float* s_in = (const float*)d_in[0];
    const float* Wc1  = (const float*)d_in[1];
    const float* Wc2  = (const float*)d_in[2];
    const float* Wc3  = (const float*)d_in[3];
    const float* Wd4a = (const float*)d_in[4];
    const float* Wd4b = (const float*)d_in[5];
    float* out = (float*)d_out;

    prep_weights<<<2400, 256>>>(Wc1, Wc2, Wc3, Wd4a, Wd4b);
    pack_input<<<(NB*2*34*TT + 255)/256, 256>>>(s_in);

    conv1_acc<<<(TT*NB*1156 + 7)/8, 256>>>();
    srm_scan_L1<<<(NB*1156 + 7)/8, 256>>>();

    pool1_acc<<<(TT*NB*289 + 7)/8, 256>>>();
    srm_scan_P1<<<(NB*289 + 7)/8, 256>>>();

    conv2_acc<<<(TT*NB*289 + 7)/8, 256>>>();
    srm_scan_L2<<<(NB*289*2 + 7)/8, 256>>>();

    pool2_acc<<<(TT*NB*81*2 + 7)/8, 256>>>();
    srm_scan_P2<<<(NB*81*2 + 7)/8, 256>>>();

    conv3_acc<<<(TT*NB*81 + 7)/8, 256>>>();
    srm_scan_L3<<<(NB*81*3 + 7)/8, 256>>>();

    pool3_acc<<<(TT*NB*25*3 + 7)/8, 256>>>();
    srm_scan_P3<<<(NB*25*3 + 7)/8, 256>>>();

    dense1<<<TT*NB, 256>>>();
    srm_scan_D1<<<(NB*8 + 7)/8, 256>>>();

    dense2<<<(TT*NB + 7)/8, 256>>>();
    srm_out<<<1, 64>>>(out);
}